// round 2
// baseline (speedup 1.0000x reference)
#include <cuda_runtime.h>

#define N_USERS  100000
#define N_ITEMS  50000
#define N_TOTAL  150000
#define DIM      64
#define NNZ      1200000
#define BATCH    4096
#define SCAN_B   1024
#define NBLK_SCAN ((N_TOTAL + SCAN_B - 1) / SCAN_B)   // 147

// ---- scratch (device globals; no allocation allowed) ----
__device__ int   g_count[N_TOTAL];
__device__ int   g_rowptr[N_TOTAL + 1];
__device__ int   g_cursor[N_TOTAL];
__device__ int   g_bsum[NBLK_SCAN];
__device__ int   g_csr_col[NNZ];
__device__ float g_csr_val[NNZ];
__device__ float g_E1[N_TOTAL * DIM];
__device__ float g_E2[N_TOTAL * DIM];

// ---------------- CSR build ----------------

__global__ void k_zero_count() {
    int i = blockIdx.x * blockDim.x + threadIdx.x;
    if (i < N_TOTAL) g_count[i] = 0;
}

__global__ void k_hist(const int* __restrict__ row) {
    int e = blockIdx.x * blockDim.x + threadIdx.x;
    if (e < NNZ) atomicAdd(&g_count[row[e]], 1);
}

// per-block exclusive scan; block totals to g_bsum
__global__ void k_scan1() {
    __shared__ int sh[SCAN_B];
    int i = blockIdx.x * SCAN_B + threadIdx.x;
    int v = (i < N_TOTAL) ? g_count[i] : 0;
    sh[threadIdx.x] = v;
    __syncthreads();
    #pragma unroll
    for (int off = 1; off < SCAN_B; off <<= 1) {
        int t = (threadIdx.x >= off) ? sh[threadIdx.x - off] : 0;
        __syncthreads();
        sh[threadIdx.x] += t;
        __syncthreads();
    }
    if (i < N_TOTAL) g_rowptr[i] = sh[threadIdx.x] - v;     // exclusive within block
    if (threadIdx.x == SCAN_B - 1) g_bsum[blockIdx.x] = sh[SCAN_B - 1];
}

// scan the 147 block sums (single thread — trivial)
__global__ void k_scan2() {
    int running = 0;
    for (int b = 0; b < NBLK_SCAN; b++) {
        int t = g_bsum[b];
        g_bsum[b] = running;
        running += t;
    }
}

__global__ void k_scan3() {
    int i = blockIdx.x * blockDim.x + threadIdx.x;
    if (i < N_TOTAL) {
        int p = g_rowptr[i] + g_bsum[i / SCAN_B];
        g_rowptr[i] = p;
        g_cursor[i] = p;
    }
    if (i == 0) g_rowptr[N_TOTAL] = NNZ;
}

__global__ void k_scatter(const int* __restrict__ row,
                          const int* __restrict__ col,
                          const float* __restrict__ val) {
    int e = blockIdx.x * blockDim.x + threadIdx.x;
    if (e < NNZ) {
        int r = row[e];
        int p = atomicAdd(&g_cursor[r], 1);
        g_csr_col[p] = col[e];
        g_csr_val[p] = val[e];
    }
}

// ---------------- SpMM: one warp per row, lane handles dims {lane, lane+32} ----------------

__device__ __forceinline__ void spmm_row(const float* __restrict__ Ein,
                                         int r, int lane,
                                         float& a0, float& a1) {
    int s = g_rowptr[r];
    int e = g_rowptr[r + 1];
    a0 = 0.f; a1 = 0.f;
    for (int j = s; j < e; j++) {
        int   c = g_csr_col[j];
        float v = g_csr_val[j];
        const float* __restrict__ ec = Ein + (size_t)c * DIM;
        a0 = fmaf(v, ec[lane],      a0);
        a1 = fmaf(v, ec[lane + 32], a1);
    }
}

__global__ void k_spmm1(const float* __restrict__ E0) {   // E1 = A @ E0
    int w    = (blockIdx.x * blockDim.x + threadIdx.x) >> 5;
    int lane = threadIdx.x & 31;
    if (w >= N_TOTAL) return;
    float a0, a1;
    spmm_row(E0, w, lane, a0, a1);
    g_E1[(size_t)w * DIM + lane]      = a0;
    g_E1[(size_t)w * DIM + lane + 32] = a1;
}

__global__ void k_spmm2() {                               // E2 = A @ E1
    int w    = (blockIdx.x * blockDim.x + threadIdx.x) >> 5;
    int lane = threadIdx.x & 31;
    if (w >= N_TOTAL) return;
    float a0, a1;
    spmm_row(g_E1, w, lane, a0, a1);
    g_E2[(size_t)w * DIM + lane]      = a0;
    g_E2[(size_t)w * DIM + lane + 32] = a1;
}

// ---------------- fused layer-3 + average + gather ----------------
// out slots: 0 u_emb, 1 pos_emb, 2 neg_emb, 3 u_emb0, 4 pos_emb0, 5 neg_emb0
__global__ void k_gather(const int* __restrict__ users,
                         const int* __restrict__ pos,
                         const int* __restrict__ neg,
                         const float* __restrict__ E0,
                         float* __restrict__ out) {
    int w    = (blockIdx.x * blockDim.x + threadIdx.x) >> 5;
    int lane = threadIdx.x & 31;
    if (w >= 3 * BATCH) return;
    int slot = w / BATCH;
    int b    = w - slot * BATCH;
    int r;
    if (slot == 0)      r = users[b];
    else if (slot == 1) r = N_USERS + pos[b];
    else                r = N_USERS + neg[b];

    // E3 row = (A @ E2)[r]  — only needed at gathered rows
    float a0, a1;
    spmm_row(g_E2, r, lane, a0, a1);

    size_t ro = (size_t)r * DIM;
    float e0a = E0[ro + lane],       e0b = E0[ro + lane + 32];
    float f0  = (e0a + g_E1[ro + lane]      + g_E2[ro + lane]      + a0) * 0.25f;
    float f1  = (e0b + g_E1[ro + lane + 32] + g_E2[ro + lane + 32] + a1) * 0.25f;

    size_t base = (size_t)slot * BATCH * DIM + (size_t)b * DIM;
    out[base + lane]      = f0;
    out[base + lane + 32] = f1;
    size_t base0 = (size_t)(slot + 3) * BATCH * DIM + (size_t)b * DIM;
    out[base0 + lane]      = e0a;
    out[base0 + lane + 32] = e0b;
}

// ---------------- launch ----------------

extern "C" void kernel_launch(void* const* d_in, const int* in_sizes, int n_in,
                              void* d_out, int out_size) {
    const int*   users = (const int*)  d_in[0];
    const int*   pos   = (const int*)  d_in[1];
    const int*   neg   = (const int*)  d_in[2];
    const float* E0    = (const float*)d_in[3];
    const int*   arow  = (const int*)  d_in[4];
    const int*   acol  = (const int*)  d_in[5];
    const float* avals = (const float*)d_in[6];
    float* out = (float*)d_out;

    k_zero_count<<<(N_TOTAL + 255) / 256, 256>>>();
    k_hist<<<(NNZ + 255) / 256, 256>>>(arow);
    k_scan1<<<NBLK_SCAN, SCAN_B>>>();
    k_scan2<<<1, 1>>>();
    k_scan3<<<(N_TOTAL + 255) / 256, 256>>>();
    k_scatter<<<(NNZ + 255) / 256, 256>>>(arow, acol, avals);

    const int spmm_blocks = (N_TOTAL * 32 + 255) / 256;   // 1 warp per row
    k_spmm1<<<spmm_blocks, 256>>>(E0);
    k_spmm2<<<spmm_blocks, 256>>>();

    const int gat_blocks = (3 * BATCH * 32 + 255) / 256;
    k_gather<<<gat_blocks, 256>>>(users, pos, neg, E0, out);
}